// round 8
// baseline (speedup 1.0000x reference)
#include <cuda_runtime.h>
#include <cstdint>

// AnchorLoss: sum over masked pairs of 1 - exp(-||p_i - p_j||^2 / 10).
// p = embedding + abs_coords, B=8, N=2048, D=2.
//
// R8: the 134 MB mask stream moves via cp.async.bulk (global->smem, mbarrier
// complete_tx) through a 3-stage ring, decoupling DRAM MLP from per-warp
// registers/scoreboards. Compute: f32x2 packed math (2 i-rows per warp per
// instruction), transposed negated point table, fused ticket reduction.

constexpr int BDIM   = 8;
constexpr int NDIM   = 2048;
constexpr int JH     = 1024;             // j per block (half row)
constexpr int WARPS  = 8;
constexpr int THREADS = 256;
constexpr int ROWS_BLK = 16;             // i-rows per block (2 per warp)
constexpr int GRID_X = NDIM / ROWS_BLK;  // 128
constexpr int NBLOCKS = GRID_X * 2 * BDIM;   // 2048
constexpr int JC   = 128;                // j-columns per stage
constexpr int NST  = JH / JC;            // 8 stages
constexpr int RING = 3;
constexpr int Q    = JH / 4;             // 256 (transposed point stride)
constexpr int STAGE_BYTES = ROWS_BLK * JC * 4;  // 8192

__device__ float g_partial[NBLOCKS];
__device__ unsigned int g_count = 0;

__device__ __forceinline__ float ex2_approx(float x) {
    float r;
    asm("ex2.approx.ftz.f32 %0, %1;" : "=f"(r) : "f"(x));
    return r;
}
__device__ __forceinline__ unsigned long long f2_add(unsigned long long a, unsigned long long b) {
    unsigned long long d;
    asm("add.rn.f32x2 %0, %1, %2;" : "=l"(d) : "l"(a), "l"(b));
    return d;
}
__device__ __forceinline__ unsigned long long f2_mul(unsigned long long a, unsigned long long b) {
    unsigned long long d;
    asm("mul.rn.f32x2 %0, %1, %2;" : "=l"(d) : "l"(a), "l"(b));
    return d;
}
__device__ __forceinline__ unsigned long long f2_fma(unsigned long long a, unsigned long long b,
                                                     unsigned long long c) {
    unsigned long long d;
    asm("fma.rn.f32x2 %0, %1, %2, %3;" : "=l"(d) : "l"(a), "l"(b), "l"(c));
    return d;
}
__device__ __forceinline__ unsigned long long f2_pack(float lo, float hi) {
    unsigned long long d;
    asm("mov.b64 %0, {%1, %2};" : "=l"(d) : "f"(lo), "f"(hi));
    return d;
}
__device__ __forceinline__ void f2_unpack(unsigned long long v, float& lo, float& hi) {
    asm("mov.b64 {%0, %1}, %2;" : "=f"(lo), "=f"(hi) : "l"(v));
}
__device__ __forceinline__ uint32_t smem_u32(const void* p) {
    uint32_t a;
    asm("{ .reg .u64 t; cvta.to.shared.u64 t, %1; cvt.u32.u64 %0, t; }"
        : "=r"(a) : "l"(p));
    return a;
}
__device__ __forceinline__ void mbar_init(uint32_t mbar, uint32_t cnt) {
    asm volatile("mbarrier.init.shared.b64 [%0], %1;" :: "r"(mbar), "r"(cnt) : "memory");
}
__device__ __forceinline__ void mbar_inval(uint32_t mbar) {
    asm volatile("mbarrier.inval.shared.b64 [%0];" :: "r"(mbar) : "memory");
}
__device__ __forceinline__ void mbar_arrive(uint32_t mbar) {
    asm volatile("mbarrier.arrive.shared.b64 _, [%0];" :: "r"(mbar) : "memory");
}
__device__ __forceinline__ void mbar_expect_tx(uint32_t mbar, uint32_t tx) {
    asm volatile("mbarrier.arrive.expect_tx.shared.b64 _, [%0], %1;"
                 :: "r"(mbar), "r"(tx) : "memory");
}
__device__ __forceinline__ void mbar_wait(uint32_t mbar, uint32_t parity) {
    uint32_t done;
    asm volatile(
        "{\n\t.reg .pred p;\n\t"
        "mbarrier.try_wait.parity.acquire.cta.shared::cta.b64 p, [%1], %2;\n\t"
        "selp.b32 %0, 1, 0, p;\n\t}"
        : "=r"(done) : "r"(mbar), "r"(parity) : "memory");
    if (!done) {
        asm volatile(
            "{\n\t.reg .pred P1;\n\t"
            "W%=:\n\t"
            "mbarrier.try_wait.parity.acquire.cta.shared::cta.b64 P1, [%0], %1, 0x989680;\n\t"
            "@P1 bra.uni D%=;\n\t"
            "bra.uni W%=;\n\t"
            "D%=:\n\t}"
            :: "r"(mbar), "r"(parity) : "memory");
    }
}
__device__ __forceinline__ void bulk_copy(uint32_t dst_smem, const void* src, uint32_t bytes,
                                          uint32_t mbar) {
    asm volatile(
        "cp.async.bulk.shared::cta.global.mbarrier::complete_tx::bytes [%0], [%1], %2, [%3];"
        :: "r"(dst_smem), "l"(src), "r"(bytes), "r"(mbar) : "memory");
}

__global__ void __launch_bounds__(THREADS, 7)
anchor_fused(const float* __restrict__ emb,
             const float* __restrict__ coords,
             const int*   __restrict__ mask,
             float*       __restrict__ out) {
    __shared__ float2 spt[JH];                       // 8 KB: (-SC*px, -SC*py), transposed by 4
    __shared__ int    smask[RING][ROWS_BLK * JC];    // 24 KB mask ring
    __shared__ unsigned long long mbars[2 * RING];   // full[0..2], empty[0..2]
    __shared__ float wsum[WARPS];
    __shared__ unsigned s_ticket;

    constexpr float SC = 0.37982825319573816f;       // sqrt(log2(e)/10)
    constexpr unsigned long long NEG1X2 = 0xBF800000BF800000ULL;

    const int tid  = threadIdx.x;
    const int warp = tid >> 5;
    const int lane = tid & 31;
    const int b    = blockIdx.z;
    const int j0   = blockIdx.y * JH;
    const int iblk = blockIdx.x * ROWS_BLK;

    const uint32_t mb = smem_u32(mbars);
    auto full_bar  = [&](int k) { return mb + 8u * k; };
    auto empty_bar = [&](int k) { return mb + 8u * (RING + k); };

    if (tid == 0) {
#pragma unroll
        for (int k = 0; k < RING; ++k) {
            mbar_init(full_bar(k), 1);
            mbar_init(empty_bar(k), THREADS);
        }
    }
    __syncthreads();

    const int* mrow_base = mask + ((size_t)b * NDIM + (size_t)iblk) * NDIM + j0;

    auto issue_stage = [&](int s) {
        const int slot = s % RING;
        mbar_expect_tx(full_bar(slot), STAGE_BYTES);
        const uint32_t dst = smem_u32(&smask[slot][0]);
        const int* src = mrow_base + s * JC;
#pragma unroll
        for (int r = 0; r < ROWS_BLK; ++r)
            bulk_copy(dst + r * JC * 4, src + (size_t)r * NDIM, JC * 4, full_bar(slot));
    };

    if (tid == 0) { issue_stage(0); issue_stage(1); issue_stage(2); }

    // Point table for this j-half, negated + prescaled, transposed by 4.
    const float2* e2 = reinterpret_cast<const float2*>(emb    + (size_t)b * NDIM * 2);
    const float2* c2 = reinterpret_cast<const float2*>(coords + (size_t)b * NDIM * 2);
    for (int t = tid; t < JH; t += THREADS) {
        float2 e = e2[j0 + t];
        float2 c = c2[j0 + t];
        spt[(t & 3) * Q + (t >> 2)] =
            make_float2(-SC * (e.x + c.x), -SC * (e.y + c.y));
    }
    __syncthreads();

    // Packed row points for this warp's two i-rows.
    const int i0 = iblk + warp * 2, i1 = i0 + 1;
    float2 ea = e2[i0], ca = c2[i0];
    float2 eb = e2[i1], cb = c2[i1];
    const unsigned long long ppx = f2_pack(SC * (ea.x + ca.x), SC * (eb.x + cb.x));
    const unsigned long long ppy = f2_pack(SC * (ea.y + ca.y), SC * (eb.y + cb.y));

    float accA = 0.0f, accB = 0.0f;
    int   cntA = 0,    cntB = 0;

#pragma unroll
    for (int s = 0; s < NST; ++s) {
        const int slot = s % RING;
        const int par  = (s / RING) & 1;

        mbar_wait(full_bar(slot), par);

        const int4* mp = reinterpret_cast<const int4*>(&smask[slot][0]);
        const int4 m0 = mp[(2 * warp)     * (JC / 4) + lane];  // LDS.128, conflict-free
        const int4 m1 = mp[(2 * warp + 1) * (JC / 4) + lane];

        const int a = s * 32 + lane;
        const float2 q0 = spt[0 * Q + a];
        const float2 q1 = spt[1 * Q + a];
        const float2 q2 = spt[2 * Q + a];
        const float2 q3 = spt[3 * Q + a];

#define PAIR(q, mA, mB)                                                        \
        {                                                                      \
            unsigned long long nx = f2_pack((q).x, (q).x);                     \
            unsigned long long ny = f2_pack((q).y, (q).y);                     \
            unsigned long long dx = f2_add(ppx, nx);                           \
            unsigned long long dy = f2_add(ppy, ny);                           \
            unsigned long long t2 = f2_mul(dx, dx);                            \
            unsigned long long ss = f2_fma(dy, dy, t2);                        \
            unsigned long long ns = f2_mul(ss, NEG1X2);                        \
            float nA, nB;                                                      \
            f2_unpack(ns, nA, nB);                                             \
            accA = fmaf((float)(mA), ex2_approx(nA), accA);                    \
            accB = fmaf((float)(mB), ex2_approx(nB), accB);                    \
            cntA += (mA); cntB += (mB);                                        \
        }
        PAIR(q0, m0.x, m1.x)
        PAIR(q1, m0.y, m1.y)
        PAIR(q2, m0.z, m1.z)
        PAIR(q3, m0.w, m1.w)
#undef PAIR

        mbar_arrive(empty_bar(slot));
        if (tid == 0 && s + RING < NST) {
            mbar_wait(empty_bar(slot), par);   // all 256 consumed this slot
            issue_stage(s + RING);
        }
    }

    float val = ((float)cntA - accA) + ((float)cntB - accB);

#pragma unroll
    for (int off = 16; off; off >>= 1)
        val += __shfl_xor_sync(0xffffffffu, val, off);
    if (lane == 0) wsum[warp] = val;
    __syncthreads();

    if (tid == 0) {
#pragma unroll
        for (int k = 0; k < RING; ++k) { mbar_inval(full_bar(k)); mbar_inval(empty_bar(k)); }
        float s = 0.0f;
#pragma unroll
        for (int w = 0; w < WARPS; ++w) s += wsum[w];
        g_partial[(blockIdx.z * 2 + blockIdx.y) * GRID_X + blockIdx.x] = s;
        __threadfence();
        s_ticket = atomicAdd(&g_count, 1u);
    }
    __syncthreads();

    // Last block: deterministic final reduction.
    if (s_ticket == NBLOCKS - 1) {
        __threadfence();
        double* sd = reinterpret_cast<double*>(spt);
        double acc = 0.0;
        for (int idx = tid; idx < NBLOCKS; idx += THREADS)
            acc += (double)g_partial[idx];
        sd[tid] = acc;
        __syncthreads();
#pragma unroll
        for (int off = THREADS / 2; off; off >>= 1) {
            if (tid < off) sd[tid] += sd[tid + off];
            __syncthreads();
        }
        if (tid == 0) {
            out[0] = (float)sd[0];
            g_count = 0;   // reset for next graph replay
        }
    }
}

extern "C" void kernel_launch(void* const* d_in, const int* in_sizes, int n_in,
                              void* d_out, int out_size) {
    const float* emb    = (const float*)d_in[0];
    const float* coords = (const float*)d_in[1];
    const int*   mask   = (const int*)d_in[2];
    float* out = (float*)d_out;

    dim3 grid(GRID_X, 2, BDIM);
    anchor_fused<<<grid, THREADS>>>(emb, coords, mask, out);
}

// round 10
// speedup vs baseline: 1.0273x; 1.0273x over previous
#include <cuda_runtime.h>
#include <cstdint>

// AnchorLoss: sum over masked pairs of 1 - exp(-||p_i - p_j||^2 / 10).
// p = embedding + abs_coords, B=8, N=2048, D=2.
//
// R10: mask (134 MB) nearly fits L2 (~126 MB); L2 persists across graph
// replays. Pin a fixed 12/16 of the mask address space with
// ld.global.nc.L2::evict_last.v4.b64 (256-bit — required form on sm_103a),
// stream the rest evict_first. LDG.256 also halves mask-load instructions.
// Body: f32x2 packed math, 2 i-rows/warp, half-j/block, fused reduction.

constexpr int BDIM = 8;
constexpr int NDIM = 2048;
constexpr int JH = NDIM / 2;          // 1024 j per block
constexpr int WARPS = 8;
constexpr int THREADS = WARPS * 32;   // 256
constexpr int ROWS_BLK = WARPS * 2;   // 16 i-rows per block
constexpr int GRID_X = NDIM / ROWS_BLK;          // 128
constexpr int NBLOCKS = GRID_X * 2 * BDIM;       // 2048
constexpr int NITER = JH / 256;                  // 4 iters: 8 j-cols per lane
constexpr int NPIN  = 3;                         // iters 0..2 evict_last (12/16 of mask)
constexpr int Q8 = JH / 8;                       // 128 (transpose-by-8 stride)

__device__ float g_partial[NBLOCKS];
__device__ unsigned int g_count = 0;

__device__ __forceinline__ float ex2_approx(float x) {
    float r;
    asm("ex2.approx.ftz.f32 %0, %1;" : "=f"(r) : "f"(x));
    return r;
}
__device__ __forceinline__ unsigned long long f2_add(unsigned long long a, unsigned long long b) {
    unsigned long long d;
    asm("add.rn.f32x2 %0, %1, %2;" : "=l"(d) : "l"(a), "l"(b));
    return d;
}
__device__ __forceinline__ unsigned long long f2_mul(unsigned long long a, unsigned long long b) {
    unsigned long long d;
    asm("mul.rn.f32x2 %0, %1, %2;" : "=l"(d) : "l"(a), "l"(b));
    return d;
}
__device__ __forceinline__ unsigned long long f2_fma(unsigned long long a, unsigned long long b,
                                                     unsigned long long c) {
    unsigned long long d;
    asm("fma.rn.f32x2 %0, %1, %2, %3;" : "=l"(d) : "l"(a), "l"(b), "l"(c));
    return d;
}
__device__ __forceinline__ unsigned long long f2_pack(float lo, float hi) {
    unsigned long long d;
    asm("mov.b64 %0, {%1, %2};" : "=l"(d) : "f"(lo), "f"(hi));
    return d;
}
__device__ __forceinline__ void f2_unpack(unsigned long long v, float& lo, float& hi) {
    asm("mov.b64 {%0, %1}, %2;" : "=f"(lo), "=f"(hi) : "l"(v));
}
// 256-bit loads with L2 eviction priority (sm_103a-legal form).
__device__ __forceinline__ longlong4 ld_keep(const void* p) {
    longlong4 v;
    asm("ld.global.nc.L2::evict_last.v4.b64 {%0,%1,%2,%3}, [%4];"
        : "=l"(v.x), "=l"(v.y), "=l"(v.z), "=l"(v.w) : "l"(p));
    return v;
}
__device__ __forceinline__ longlong4 ld_stream(const void* p) {
    longlong4 v;
    asm("ld.global.nc.L2::evict_first.v4.b64 {%0,%1,%2,%3}, [%4];"
        : "=l"(v.x), "=l"(v.y), "=l"(v.z), "=l"(v.w) : "l"(p));
    return v;
}

__global__ void __launch_bounds__(THREADS, 7)
anchor_fused(const float* __restrict__ emb,
             const float* __restrict__ coords,
             const int*   __restrict__ mask,
             float*       __restrict__ out) {
    // sq[(j&7)*Q8 + (j>>3)] = {-sx,-sx,-sy,-sy} for point j of this half (16 KB)
    __shared__ float4 sq[JH];
    __shared__ float wsum[WARPS];
    __shared__ unsigned s_ticket;

    constexpr float SC = 0.37982825319573816f;  // sqrt(log2(e)/10)
    constexpr unsigned long long NEG1X2 = 0xBF800000BF800000ULL;  // {-1.f,-1.f}

    const int b  = blockIdx.z;
    const int j0 = blockIdx.y * JH;     // j-half origin

    const float2* e2 = reinterpret_cast<const float2*>(emb    + (size_t)b * NDIM * 2);
    const float2* c2 = reinterpret_cast<const float2*>(coords + (size_t)b * NDIM * 2);

    for (int t = threadIdx.x; t < JH; t += THREADS) {
        float2 e = e2[j0 + t];
        float2 c = c2[j0 + t];
        float nx = -SC * (e.x + c.x), ny = -SC * (e.y + c.y);
        sq[(t & 7) * Q8 + (t >> 3)] = make_float4(nx, nx, ny, ny);
    }
    __syncthreads();

    const int warp = threadIdx.x >> 5;
    const int lane = threadIdx.x & 31;
    const int i0 = blockIdx.x * ROWS_BLK + warp * 2;
    const int i1 = i0 + 1;

    float2 ea = e2[i0], ca = c2[i0];
    float2 eb = e2[i1], cb = c2[i1];
    const unsigned long long ppx = f2_pack(SC * (ea.x + ca.x), SC * (eb.x + cb.x));
    const unsigned long long ppy = f2_pack(SC * (ea.y + ca.y), SC * (eb.y + cb.y));

    const int* mrow0 = mask + ((size_t)b * NDIM + (size_t)i0) * NDIM + j0;
    const int* mrow1 = mask + ((size_t)b * NDIM + (size_t)i1) * NDIM + j0;
    const ulonglong2* sqv = reinterpret_cast<const ulonglong2*>(sq);

    float accA = 0.0f, accB = 0.0f;
    int   cntA = 0,    cntB = 0;

#pragma unroll
    for (int it = 0; it < NITER; ++it) {
        const int a = it * 32 + lane;       // 8-column group index within the half
        // Fixed address split: first 3/4 of each row segment is the pinned
        // L2-resident set; the last 1/4 streams with evict_first.
        union { longlong4 v; int m[8]; } u0, u1;
        if (it < NPIN) {
            u0.v = ld_keep(mrow0 + 8 * a);
            u1.v = ld_keep(mrow1 + 8 * a);
        } else {
            u0.v = ld_stream(mrow0 + 8 * a);
            u1.v = ld_stream(mrow1 + 8 * a);
        }

#define PAIR(k)                                                                \
        {                                                                      \
            const ulonglong2 v = sqv[(k) * Q8 + a];   /* LDS.128, no conflict */\
            unsigned long long dx = f2_add(ppx, v.x); /* both rows at once  */ \
            unsigned long long dy = f2_add(ppy, v.y);                          \
            unsigned long long t  = f2_mul(dx, dx);                            \
            unsigned long long s  = f2_fma(dy, dy, t);                         \
            unsigned long long ns = f2_mul(s, NEG1X2);                         \
            float nsA, nsB;                                                    \
            f2_unpack(ns, nsA, nsB);                                           \
            accA = fmaf((float)u0.m[k], ex2_approx(nsA), accA);                \
            accB = fmaf((float)u1.m[k], ex2_approx(nsB), accB);                \
            cntA += u0.m[k]; cntB += u1.m[k];                                  \
        }
        PAIR(0) PAIR(1) PAIR(2) PAIR(3)
        PAIR(4) PAIR(5) PAIR(6) PAIR(7)
#undef PAIR
    }

    float val = ((float)cntA - accA) + ((float)cntB - accB);

    // warp reduce
#pragma unroll
    for (int off = 16; off; off >>= 1)
        val += __shfl_xor_sync(0xffffffffu, val, off);

    if (lane == 0) wsum[warp] = val;
    __syncthreads();

    if (threadIdx.x == 0) {
        float s = 0.0f;
#pragma unroll
        for (int w = 0; w < WARPS; ++w) s += wsum[w];
        g_partial[(blockIdx.z * 2 + blockIdx.y) * GRID_X + blockIdx.x] = s;
        __threadfence();
        s_ticket = atomicAdd(&g_count, 1u);
    }
    __syncthreads();

    // Last block performs the deterministic final reduction.
    if (s_ticket == NBLOCKS - 1) {
        __threadfence();  // make all g_partial writes visible
        double* sd = reinterpret_cast<double*>(sq);  // reuse smem
        double acc = 0.0;
        for (int idx = threadIdx.x; idx < NBLOCKS; idx += THREADS)
            acc += (double)g_partial[idx];
        sd[threadIdx.x] = acc;
        __syncthreads();
#pragma unroll
        for (int off = THREADS / 2; off; off >>= 1) {
            if (threadIdx.x < off) sd[threadIdx.x] += sd[threadIdx.x + off];
            __syncthreads();
        }
        if (threadIdx.x == 0) {
            out[0] = (float)sd[0];
            g_count = 0;   // reset for next graph replay
        }
    }
}

extern "C" void kernel_launch(void* const* d_in, const int* in_sizes, int n_in,
                              void* d_out, int out_size) {
    const float* emb    = (const float*)d_in[0];
    const float* coords = (const float*)d_in[1];
    const int*   mask   = (const int*)d_in[2];
    float* out = (float*)d_out;

    dim3 grid(GRID_X, 2, BDIM);
    anchor_fused<<<grid, THREADS>>>(emb, coords, mask, out);
}

// round 11
// speedup vs baseline: 1.1947x; 1.1630x over previous
#include <cuda_runtime.h>
#include <cstdint>

// AnchorLoss: sum over masked pairs of 1 - exp(-||p_i - p_j||^2 / 10),
// p = embedding + abs_coords, B=8, N=2048, D=2.
//
// Measured-best configuration (R1 shape): transposed float2 point cache
// (16 KB -> 8 blocks/SM), 1 i-row per warp, __ldcs int4 mask loads,
// I2F+FFMA gating, unroll 4, separate warm reduce kernel (graph replay
// makes the 2nd launch ~1us; fusing it into the hot kernel measured SLOWER).
// Reduce kernel: 1024 threads, 2 parallel loads each, shfl+smem double tree.

constexpr int BDIM = 8;
constexpr int NDIM = 2048;
constexpr int ROWS = 8;            // i-rows per block (one warp per row)
constexpr int THREADS = ROWS * 32; // 256
constexpr int GRID_X = NDIM / ROWS;       // 256
constexpr int NBLOCKS = GRID_X * BDIM;    // 2048
constexpr int Q = NDIM / 4;               // 512 (transposed stride)

__device__ float g_partial[NBLOCKS];

__device__ __forceinline__ float ex2_approx(float x) {
    float r;
    asm("ex2.approx.ftz.f32 %0, %1;" : "=f"(r) : "f"(x));
    return r;
}

__global__ void __launch_bounds__(THREADS, 8)
anchor_main(const float* __restrict__ emb,
            const float* __restrict__ coords,
            const int*   __restrict__ mask) {
    // Transposed point cache: sp[(j&3)*Q + (j>>2)] = p[j]
    __shared__ float2 sp[NDIM];
    __shared__ float wsum[ROWS];

    const int b = blockIdx.y;
    const float2* e2 = reinterpret_cast<const float2*>(emb    + (size_t)b * NDIM * 2);
    const float2* c2 = reinterpret_cast<const float2*>(coords + (size_t)b * NDIM * 2);
    for (int t = threadIdx.x; t < NDIM; t += THREADS) {
        float2 e = e2[t];
        float2 c = c2[t];
        sp[(t & 3) * Q + (t >> 2)] = make_float2(e.x + c.x, e.y + c.y);
    }
    __syncthreads();

    const int warp = threadIdx.x >> 5;
    const int lane = threadIdx.x & 31;
    const int i = blockIdx.x * ROWS + warp;

    const float2 pi = sp[(i & 3) * Q + (i >> 2)];
    const int4* mrow = reinterpret_cast<const int4*>(
        mask + ((size_t)b * NDIM + (size_t)i) * NDIM);

    constexpr float NEGC = -0.14426950408889634f;  // -log2(e)/TEMPERATURE

    float accE = 0.0f;  // sum of m * exp(...)
    int   cnt  = 0;     // count of m==1

#pragma unroll 4
    for (int it = 0; it < NDIM / 128; ++it) {  // 16 iterations
        const int a = it * 32 + lane;          // int4 index == transposed index
        const int4 m = __ldcs(&mrow[a]);       // masks for j = 4a .. 4a+3

        const float2 p0 = sp[0 * Q + a];
        const float2 p1 = sp[1 * Q + a];
        const float2 p2 = sp[2 * Q + a];
        const float2 p3 = sp[3 * Q + a];

        {
            float dx = pi.x - p0.x, dy = pi.y - p0.y;
            float arg = fmaf(dy, dy, dx * dx) * NEGC;
            accE = fmaf((float)m.x, ex2_approx(arg), accE);
            cnt += m.x;
        }
        {
            float dx = pi.x - p1.x, dy = pi.y - p1.y;
            float arg = fmaf(dy, dy, dx * dx) * NEGC;
            accE = fmaf((float)m.y, ex2_approx(arg), accE);
            cnt += m.y;
        }
        {
            float dx = pi.x - p2.x, dy = pi.y - p2.y;
            float arg = fmaf(dy, dy, dx * dx) * NEGC;
            accE = fmaf((float)m.z, ex2_approx(arg), accE);
            cnt += m.z;
        }
        {
            float dx = pi.x - p3.x, dy = pi.y - p3.y;
            float arg = fmaf(dy, dy, dx * dx) * NEGC;
            accE = fmaf((float)m.w, ex2_approx(arg), accE);
            cnt += m.w;
        }
    }

    float val = (float)cnt - accE;

    // warp reduce
#pragma unroll
    for (int off = 16; off; off >>= 1)
        val += __shfl_xor_sync(0xffffffffu, val, off);

    if (lane == 0) wsum[warp] = val;
    __syncthreads();

    if (threadIdx.x == 0) {
        float s = 0.0f;
#pragma unroll
        for (int w = 0; w < ROWS; ++w) s += wsum[w];
        g_partial[blockIdx.y * GRID_X + blockIdx.x] = s;
    }
}

// 1024 threads, one block. Each thread loads 2 partials (independent loads,
// single latency round — g_partial is L2-warm in the timed loop), then a
// deterministic double-precision shfl + smem tree.
__global__ void __launch_bounds__(1024)
anchor_reduce(float* __restrict__ out) {
    __shared__ double s[32];
    const int t    = threadIdx.x;
    const int lane = t & 31;
    const int warp = t >> 5;

    double acc = (double)g_partial[t] + (double)g_partial[t + 1024];

#pragma unroll
    for (int off = 16; off; off >>= 1)
        acc += __shfl_xor_sync(0xffffffffu, acc, off);

    if (lane == 0) s[warp] = acc;
    __syncthreads();

    if (warp == 0) {
        double v = s[lane];
#pragma unroll
        for (int off = 16; off; off >>= 1)
            v += __shfl_xor_sync(0xffffffffu, v, off);
        if (lane == 0) out[0] = (float)v;
    }
}

extern "C" void kernel_launch(void* const* d_in, const int* in_sizes, int n_in,
                              void* d_out, int out_size) {
    const float* emb    = (const float*)d_in[0];
    const float* coords = (const float*)d_in[1];
    const int*   mask   = (const int*)d_in[2];
    float* out = (float*)d_out;

    dim3 grid(GRID_X, BDIM);
    anchor_main<<<grid, THREADS>>>(emb, coords, mask);
    anchor_reduce<<<1, 1024>>>(out);
}